// round 1
// baseline (speedup 1.0000x reference)
#include <cuda_runtime.h>

constexpr int Hc = 128, Wc = 128, HWc = Hc * Wc;

// ---------------- scratch (device globals; no allocation allowed) ----------------
__device__ float g_h1[2 * 64 * HWc];
__device__ float g_h2[2 * 64 * HWc];
__device__ float g_po[2 * 432 * HWc];

// ---------------- packed f32x2 helpers ----------------
__device__ __forceinline__ unsigned long long pack2(float lo, float hi) {
    unsigned long long r;
    asm("mov.b64 %0, {%1, %2};" : "=l"(r) : "f"(lo), "f"(hi));
    return r;
}
__device__ __forceinline__ void unpack2(unsigned long long v, float& lo, float& hi) {
    asm("mov.b64 {%0, %1}, %2;" : "=f"(lo), "=f"(hi) : "l"(v));
}
__device__ __forceinline__ void fma2(unsigned long long& d, unsigned long long a, unsigned long long b) {
    asm("fma.rn.f32x2 %0, %1, %2, %0;" : "+l"(d) : "l"(a), "l"(b));
}

// ---------------- direct 3x3 conv, smem-tiled, f32x2 accumulators ----------------
// Grid: (W/32, H/8, B*NCOB). Block 256 = 32x8 pixel tile. Each thread: COUT_BLK outputs.
template <int CIN, int COUT_BLK, int NCOB, bool LEAKY, bool TRANSFORM>
__global__ __launch_bounds__(256)
void conv3x3_kernel(const float* __restrict__ in, const float* __restrict__ wgt,
                    const float* __restrict__ bias, float* __restrict__ out,
                    const float* __restrict__ flow)
{
    constexpr int TW = 32, TH = 8, CK = 8;
    constexpr int NACC = COUT_BLK / 2;
    constexpr int COUT_TOT = COUT_BLK * NCOB;

    __shared__ float s_in[CK][TH + 2][TW + 2];
    __shared__ float s_wt[CK * 9 * COUT_BLK];  // [ci][k][co], co contiguous

    const int bz  = blockIdx.z;
    const int b   = bz / NCOB;
    const int coz = bz % NCOB;
    const int x0  = blockIdx.x * TW;
    const int y0  = blockIdx.y * TH;
    const int tid = threadIdx.x;
    const int tx  = tid % TW;
    const int ty  = tid / TW;
    const int xx  = x0 + tx, yy = y0 + ty;

    unsigned long long acc[NACC];
    {
        const float* bp = bias + coz * COUT_BLK;
        #pragma unroll
        for (int j = 0; j < NACC; j++) acc[j] = pack2(bp[2 * j], bp[2 * j + 1]);
    }

    for (int cb = 0; cb < CIN; cb += CK) {
        __syncthreads();
        const float* ip = in + (b * CIN + cb) * HWc;
        #pragma unroll 1
        for (int i = tid; i < CK * (TH + 2) * (TW + 2); i += 256) {
            int lx = i % (TW + 2);
            int r  = i / (TW + 2);
            int ly = r % (TH + 2);
            int ci = r / (TH + 2);
            int gx = x0 + lx - 1, gy = y0 + ly - 1;
            float v = 0.f;
            if ((unsigned)gx < (unsigned)Wc && (unsigned)gy < (unsigned)Hc)
                v = ip[ci * HWc + gy * Wc + gx];
            s_in[ci][ly][lx] = v;
        }
        #pragma unroll 1
        for (int i = tid; i < CK * 9 * COUT_BLK; i += 256) {
            int co = i % COUT_BLK;
            int r  = i / COUT_BLK;
            int k  = r % 9;
            int ci = r / 9;
            s_wt[i] = wgt[((coz * COUT_BLK + co) * CIN + (cb + ci)) * 9 + k];
        }
        __syncthreads();

        #pragma unroll 1
        for (int ci = 0; ci < CK; ci++) {
            float v[9];
            #pragma unroll
            for (int dy = 0; dy < 3; dy++) {
                #pragma unroll
                for (int dx = 0; dx < 3; dx++) {
                    v[dy * 3 + dx] = s_in[ci][ty + dy][tx + dx];
                }
            }
            #pragma unroll
            for (int k = 0; k < 9; k++) {
                unsigned long long vv = pack2(v[k], v[k]);
                const ulonglong2* wp =
                    reinterpret_cast<const ulonglong2*>(&s_wt[(ci * 9 + k) * COUT_BLK]);
                #pragma unroll
                for (int j = 0; j < NACC / 2; j++) {
                    ulonglong2 w2 = wp[j];
                    fma2(acc[2 * j],     w2.x, vv);
                    fma2(acc[2 * j + 1], w2.y, vv);
                }
            }
        }
    }

    float fy = 0.f, fx = 0.f;
    if (TRANSFORM) {
        // flow_yx channel 0 = flow[:,1] (y), channel 1 = flow[:,0] (x)
        fy = flow[(b * 2 + 1) * HWc + yy * Wc + xx];
        fx = flow[(b * 2 + 0) * HWc + yy * Wc + xx];
    }
    #pragma unroll
    for (int j = 0; j < NACC; j++) {
        float r0, r1;
        unpack2(acc[j], r0, r1);
        float rv[2] = {r0, r1};
        #pragma unroll
        for (int t = 0; t < 2; t++) {
            int co = coz * COUT_BLK + 2 * j + t;
            float v = rv[t];
            if (LEAKY) v = (v >= 0.f) ? v : 0.1f * v;
            if (TRANSFORM) {
                if (co < 288) v = 10.f * tanhf(v) + ((co & 1) ? fx : fy);
                else          v = 1.f / (1.f + expf(-v));
            }
            out[(b * COUT_TOT + co) * HWc + yy * Wc + xx] = v;
        }
    }
}

// ---------------- deformable gather + einsum ----------------
// Grid (8,16,B), block 128 = 16x8 pixel tile. Each thread: one pixel, 64 outputs
// in 32 packed f32x2 accumulators. Weights staged 4 groups at a time in smem.
__global__ __launch_bounds__(128)
void deform_kernel(const float* __restrict__ xin, const float* __restrict__ po,
                   const float* __restrict__ wgt, float* __restrict__ out)
{
    __shared__ float s_wt[4 * 9 * 4 * 64];  // [gl][k][c][o]

    const int b   = blockIdx.z;
    const int x0  = blockIdx.x * 16, y0 = blockIdx.y * 8;
    const int tid = threadIdx.x;
    const int tx  = tid % 16, ty = tid / 16;
    const int xx  = x0 + tx, yy = y0 + ty;

    unsigned long long acc[32];
    #pragma unroll
    for (int j = 0; j < 32; j++) acc[j] = 0ULL;

    const float* pob = po + b * 432 * HWc + yy * Wc + xx;
    const float* xb  = xin + b * 64 * HWc;

    #pragma unroll 1
    for (int gb = 0; gb < 16; gb += 4) {
        __syncthreads();
        #pragma unroll 1
        for (int i = tid; i < 4 * 9 * 4 * 64; i += 128) {
            int o = i & 63;
            int r = i >> 6;
            int c = r & 3;
            r >>= 2;
            int k  = r % 9;
            int gl = r / 9;
            // wk[o][g][c][k] = weight[(o*64 + g*4 + c)*9 + k]
            s_wt[i] = wgt[(o * 64 + (gb + gl) * 4 + c) * 9 + k];
        }
        __syncthreads();

        #pragma unroll 1
        for (int gl = 0; gl < 4; gl++) {
            const int g = gb + gl;
            const float* xg = xb + g * 4 * HWc;
            #pragma unroll 1
            for (int k = 0; k < 9; k++) {
                const int gk = g * 9 + k;
                float offy = pob[(2 * gk) * HWc];
                float offx = pob[(2 * gk + 1) * HWc];
                float msk  = pob[(288 + gk) * HWc];

                float py = (float)(yy + k / 3 - 1) + offy;
                float px = (float)(xx + k % 3 - 1) + offx;
                float fy = floorf(py), fxv = floorf(px);
                int iy0 = (int)fy, ix0 = (int)fxv;
                float wy = py - fy, wx = px - fxv;

                bool vy0 = (unsigned)iy0       < (unsigned)Hc;
                bool vy1 = (unsigned)(iy0 + 1) < (unsigned)Hc;
                bool vx0 = (unsigned)ix0       < (unsigned)Wc;
                bool vx1 = (unsigned)(ix0 + 1) < (unsigned)Wc;
                int cy0 = min(max(iy0, 0), Hc - 1), cy1 = min(max(iy0 + 1, 0), Hc - 1);
                int cx0 = min(max(ix0, 0), Wc - 1), cx1 = min(max(ix0 + 1, 0), Wc - 1);

                float w00 = (1.f - wy) * (1.f - wx) * msk; if (!(vy0 && vx0)) w00 = 0.f;
                float w01 = (1.f - wy) * wx        * msk; if (!(vy0 && vx1)) w01 = 0.f;
                float w10 = wy        * (1.f - wx) * msk; if (!(vy1 && vx0)) w10 = 0.f;
                float w11 = wy        * wx         * msk; if (!(vy1 && vx1)) w11 = 0.f;

                int i00 = cy0 * Wc + cx0, i01 = cy0 * Wc + cx1;
                int i10 = cy1 * Wc + cx0, i11 = cy1 * Wc + cx1;

                #pragma unroll
                for (int c = 0; c < 4; c++) {
                    const float* p = xg + c * HWc;
                    float val = w00 * __ldg(p + i00) + w01 * __ldg(p + i01)
                              + w10 * __ldg(p + i10) + w11 * __ldg(p + i11);
                    unsigned long long vv = pack2(val, val);
                    const ulonglong2* wp = reinterpret_cast<const ulonglong2*>(
                        &s_wt[((gl * 9 + k) * 4 + c) * 64]);
                    #pragma unroll
                    for (int j = 0; j < 16; j++) {
                        ulonglong2 w2 = wp[j];
                        fma2(acc[2 * j],     w2.x, vv);
                        fma2(acc[2 * j + 1], w2.y, vv);
                    }
                }
            }
        }
    }

    #pragma unroll
    for (int j = 0; j < 32; j++) {
        float lo, hi;
        unpack2(acc[j], lo, hi);
        out[(b * 64 + 2 * j)     * HWc + yy * Wc + xx] = lo;
        out[(b * 64 + 2 * j + 1) * HWc + yy * Wc + xx] = hi;
    }
}

// ---------------- launch ----------------
extern "C" void kernel_launch(void* const* d_in, const int* in_sizes, int n_in,
                              void* d_out, int out_size)
{
    const float* x    = (const float*)d_in[0];
    const float* ef   = (const float*)d_in[1];
    const float* flow = (const float*)d_in[2];
    const float* w1   = (const float*)d_in[3];
    const float* b1   = (const float*)d_in[4];
    const float* w2   = (const float*)d_in[5];
    const float* b2   = (const float*)d_in[6];
    const float* w3   = (const float*)d_in[7];
    const float* b3   = (const float*)d_in[8];
    const float* wgt  = (const float*)d_in[9];
    float* out = (float*)d_out;

    const int B = in_sizes[0] / (64 * HWc);  // = 2

    float *h1, *h2, *ppo;
    cudaGetSymbolAddress((void**)&h1,  g_h1);
    cudaGetSymbolAddress((void**)&h2,  g_h2);
    cudaGetSymbolAddress((void**)&ppo, g_po);

    // conv1: 128 -> 64, leaky
    conv3x3_kernel<128, 64, 1, true, false><<<dim3(4, 16, B), 256>>>(ef, w1, b1, h1, nullptr);
    // conv2: 64 -> 64, leaky
    conv3x3_kernel<64, 64, 1, true, false><<<dim3(4, 16, B), 256>>>(h1, w2, b2, h2, nullptr);
    // conv3: 64 -> 432, fused tanh/flow/sigmoid epilogue (off = o[:, :288] identity)
    conv3x3_kernel<64, 48, 9, false, true><<<dim3(4, 16, B * 9), 256>>>(h2, w3, b3, ppo, flow);
    // deformable gather + einsum
    deform_kernel<<<dim3(8, 16, B), 128>>>(x, ppo, wgt, out);
}

// round 2
// speedup vs baseline: 1.1943x; 1.1943x over previous
#include <cuda_runtime.h>

constexpr int Hc = 128, Wc = 128, HWc = Hc * Wc;

// ---------------- scratch (device globals; no allocation allowed) ----------------
__device__ float g_h1[2 * 64 * HWc];
__device__ float g_h2[2 * 64 * HWc];
__device__ float g_po[2 * 432 * HWc];
__device__ float g_dp[2 * 2 * 64 * HWc];   // [split][b][co][hw]

// ---------------- packed f32x2 helpers ----------------
__device__ __forceinline__ unsigned long long pack2(float lo, float hi) {
    unsigned long long r;
    asm("mov.b64 %0, {%1, %2};" : "=l"(r) : "f"(lo), "f"(hi));
    return r;
}
__device__ __forceinline__ void unpack2(unsigned long long v, float& lo, float& hi) {
    asm("mov.b64 {%0, %1}, %2;" : "=f"(lo), "=f"(hi) : "l"(v));
}
__device__ __forceinline__ void fma2(unsigned long long& d, unsigned long long a, unsigned long long b) {
    asm("fma.rn.f32x2 %0, %1, %2, %0;" : "+l"(d) : "l"(a), "l"(b));
}

// ---------------- direct 3x3 conv, smem-tiled, 2 pixels/thread ----------------
// Block 256 = 32x8 threads; tile = 32 wide x 16 tall (each thread: rows ty, ty+8).
// Grid: (W/32, H/16, B*NCOB). Each thread: COUT_BLK outputs x 2 pixels.
template <int CIN, int COUT_BLK, int NCOB, bool LEAKY, bool TRANSFORM>
__global__ __launch_bounds__(256)
void conv3x3_kernel(const float* __restrict__ in, const float* __restrict__ wgt,
                    const float* __restrict__ bias, float* __restrict__ out,
                    const float* __restrict__ flow)
{
    constexpr int TW = 32, THROWS = 16, CK = 8;
    constexpr int NACC = COUT_BLK / 2;
    constexpr int COUT_TOT = COUT_BLK * NCOB;

    __shared__ float s_in[CK][THROWS + 2][TW + 2];
    __shared__ float s_wt[CK * 9 * COUT_BLK];  // [ci][k][co], co contiguous

    const int bz  = blockIdx.z;
    const int b   = bz / NCOB;
    const int coz = bz % NCOB;
    const int x0  = blockIdx.x * TW;
    const int y0  = blockIdx.y * THROWS;
    const int tid = threadIdx.x;
    const int tx  = tid % TW;
    const int ty  = tid / TW;               // 0..7
    const int xx  = x0 + tx;
    const int yy0 = y0 + ty, yy1 = y0 + ty + 8;

    unsigned long long acc0[NACC], acc1[NACC];
    {
        const float* bp = bias + coz * COUT_BLK;
        #pragma unroll
        for (int j = 0; j < NACC; j++) {
            unsigned long long bv = pack2(bp[2 * j], bp[2 * j + 1]);
            acc0[j] = bv; acc1[j] = bv;
        }
    }

    for (int cb = 0; cb < CIN; cb += CK) {
        __syncthreads();
        const float* ip = in + (b * CIN + cb) * HWc;
        #pragma unroll 1
        for (int i = tid; i < CK * (THROWS + 2) * (TW + 2); i += 256) {
            int lx = i % (TW + 2);
            int r  = i / (TW + 2);
            int ly = r % (THROWS + 2);
            int ci = r / (THROWS + 2);
            int gx = x0 + lx - 1, gy = y0 + ly - 1;
            float v = 0.f;
            if ((unsigned)gx < (unsigned)Wc && (unsigned)gy < (unsigned)Hc)
                v = ip[ci * HWc + gy * Wc + gx];
            s_in[ci][ly][lx] = v;
        }
        #pragma unroll 1
        for (int i = tid; i < CK * 9 * COUT_BLK; i += 256) {
            int co = i % COUT_BLK;
            int r  = i / COUT_BLK;
            int k  = r % 9;
            int ci = r / 9;
            s_wt[i] = wgt[((coz * COUT_BLK + co) * CIN + (cb + ci)) * 9 + k];
        }
        __syncthreads();

        #pragma unroll 1
        for (int ci = 0; ci < CK; ci++) {
            float v0[9], v1[9];
            #pragma unroll
            for (int dy = 0; dy < 3; dy++) {
                #pragma unroll
                for (int dx = 0; dx < 3; dx++) {
                    v0[dy * 3 + dx] = s_in[ci][ty + dy][tx + dx];
                    v1[dy * 3 + dx] = s_in[ci][ty + 8 + dy][tx + dx];
                }
            }
            #pragma unroll
            for (int k = 0; k < 9; k++) {
                unsigned long long vv0 = pack2(v0[k], v0[k]);
                unsigned long long vv1 = pack2(v1[k], v1[k]);
                const ulonglong2* wp =
                    reinterpret_cast<const ulonglong2*>(&s_wt[(ci * 9 + k) * COUT_BLK]);
                #pragma unroll
                for (int j = 0; j < NACC / 2; j++) {
                    ulonglong2 w2 = wp[j];
                    fma2(acc0[2 * j],     w2.x, vv0);
                    fma2(acc0[2 * j + 1], w2.y, vv0);
                    fma2(acc1[2 * j],     w2.x, vv1);
                    fma2(acc1[2 * j + 1], w2.y, vv1);
                }
            }
        }
    }

    float fy0 = 0.f, fx0 = 0.f, fy1 = 0.f, fx1 = 0.f;
    if (TRANSFORM) {
        fy0 = flow[(b * 2 + 1) * HWc + yy0 * Wc + xx];
        fx0 = flow[(b * 2 + 0) * HWc + yy0 * Wc + xx];
        fy1 = flow[(b * 2 + 1) * HWc + yy1 * Wc + xx];
        fx1 = flow[(b * 2 + 0) * HWc + yy1 * Wc + xx];
    }
    #pragma unroll
    for (int j = 0; j < NACC; j++) {
        float r00, r01, r10, r11;
        unpack2(acc0[j], r00, r01);
        unpack2(acc1[j], r10, r11);
        float rv0[2] = {r00, r01};
        float rv1[2] = {r10, r11};
        #pragma unroll
        for (int t = 0; t < 2; t++) {
            int co = coz * COUT_BLK + 2 * j + t;
            float a = rv0[t], c = rv1[t];
            if (LEAKY) {
                a = (a >= 0.f) ? a : 0.1f * a;
                c = (c >= 0.f) ? c : 0.1f * c;
            }
            if (TRANSFORM) {
                if (co < 288) {
                    a = 10.f * tanhf(a) + ((co & 1) ? fx0 : fy0);
                    c = 10.f * tanhf(c) + ((co & 1) ? fx1 : fy1);
                } else {
                    a = 1.f / (1.f + expf(-a));
                    c = 1.f / (1.f + expf(-c));
                }
            }
            out[(b * COUT_TOT + co) * HWc + yy0 * Wc + xx] = a;
            out[(b * COUT_TOT + co) * HWc + yy1 * Wc + xx] = c;
        }
    }
}

// ---------------- deformable gather + einsum (group-split partials) ----------------
// Grid (8,16,B*NSPLIT), block 128 = 16x8 pixel tile. Each block handles 8 groups,
// writes partial 64-channel sums to g_dp[split]. k-loop unrolled x3 for MLP.
constexpr int NSPLIT = 2;
constexpr int GPS = 16 / NSPLIT;   // groups per split = 8

__global__ __launch_bounds__(128)
void deform_kernel(const float* __restrict__ xin, const float* __restrict__ po,
                   const float* __restrict__ wgt, float* __restrict__ dp)
{
    __shared__ float s_wt[4 * 9 * 4 * 64];  // [gl][k][c][o]

    const int bz    = blockIdx.z;
    const int b     = bz / NSPLIT;
    const int split = bz % NSPLIT;
    const int g0    = split * GPS;
    const int x0    = blockIdx.x * 16, y0 = blockIdx.y * 8;
    const int tid   = threadIdx.x;
    const int tx    = tid % 16, ty = tid / 16;
    const int xx    = x0 + tx, yy = y0 + ty;

    unsigned long long acc[32];
    #pragma unroll
    for (int j = 0; j < 32; j++) acc[j] = 0ULL;

    const float* pob = po + b * 432 * HWc + yy * Wc + xx;
    const float* xb  = xin + b * 64 * HWc;

    #pragma unroll 1
    for (int gb = 0; gb < GPS; gb += 4) {
        __syncthreads();
        #pragma unroll 1
        for (int i = tid; i < 4 * 9 * 4 * 64; i += 128) {
            int o = i & 63;
            int r = i >> 6;
            int c = r & 3;
            r >>= 2;
            int k  = r % 9;
            int gl = r / 9;
            s_wt[i] = wgt[(o * 64 + (g0 + gb + gl) * 4 + c) * 9 + k];
        }
        __syncthreads();

        #pragma unroll 1
        for (int gl = 0; gl < 4; gl++) {
            const int g = g0 + gb + gl;
            const float* xg = xb + g * 4 * HWc;
            #pragma unroll 3
            for (int k = 0; k < 9; k++) {
                const int gk = g * 9 + k;
                float offy = pob[(2 * gk) * HWc];
                float offx = pob[(2 * gk + 1) * HWc];
                float msk  = pob[(288 + gk) * HWc];

                float py = (float)(yy + k / 3 - 1) + offy;
                float px = (float)(xx + k % 3 - 1) + offx;
                float fy = floorf(py), fxv = floorf(px);
                int iy0 = (int)fy, ix0 = (int)fxv;
                float wy = py - fy, wx = px - fxv;

                bool vy0 = (unsigned)iy0       < (unsigned)Hc;
                bool vy1 = (unsigned)(iy0 + 1) < (unsigned)Hc;
                bool vx0 = (unsigned)ix0       < (unsigned)Wc;
                bool vx1 = (unsigned)(ix0 + 1) < (unsigned)Wc;
                int cy0 = min(max(iy0, 0), Hc - 1), cy1 = min(max(iy0 + 1, 0), Hc - 1);
                int cx0 = min(max(ix0, 0), Wc - 1), cx1 = min(max(ix0 + 1, 0), Wc - 1);

                float w00 = (1.f - wy) * (1.f - wx) * msk; if (!(vy0 && vx0)) w00 = 0.f;
                float w01 = (1.f - wy) * wx        * msk; if (!(vy0 && vx1)) w01 = 0.f;
                float w10 = wy        * (1.f - wx) * msk; if (!(vy1 && vx0)) w10 = 0.f;
                float w11 = wy        * wx         * msk; if (!(vy1 && vx1)) w11 = 0.f;

                int i00 = cy0 * Wc + cx0, i01 = cy0 * Wc + cx1;
                int i10 = cy1 * Wc + cx0, i11 = cy1 * Wc + cx1;

                #pragma unroll
                for (int c = 0; c < 4; c++) {
                    const float* p = xg + c * HWc;
                    float val = w00 * __ldg(p + i00) + w01 * __ldg(p + i01)
                              + w10 * __ldg(p + i10) + w11 * __ldg(p + i11);
                    unsigned long long vv = pack2(val, val);
                    const ulonglong2* wp = reinterpret_cast<const ulonglong2*>(
                        &s_wt[((gl * 9 + k) * 4 + c) * 64]);
                    #pragma unroll
                    for (int j = 0; j < 16; j++) {
                        ulonglong2 w2 = wp[j];
                        fma2(acc[2 * j],     w2.x, vv);
                        fma2(acc[2 * j + 1], w2.y, vv);
                    }
                }
            }
        }
    }

    float* dpo = dp + (split * 2 + b) * 64 * HWc;
    #pragma unroll
    for (int j = 0; j < 32; j++) {
        float lo, hi;
        unpack2(acc[j], lo, hi);
        dpo[(2 * j)     * HWc + yy * Wc + xx] = lo;
        dpo[(2 * j + 1) * HWc + yy * Wc + xx] = hi;
    }
}

// ---------------- combine partials ----------------
__global__ __launch_bounds__(256)
void combine_kernel(const float* __restrict__ dp, float* __restrict__ out, int n4)
{
    int i = blockIdx.x * 256 + threadIdx.x;
    if (i < n4) {
        float4 a = reinterpret_cast<const float4*>(dp)[i];
        float4 c = reinterpret_cast<const float4*>(dp)[n4 + i];
        float4 o;
        o.x = a.x + c.x; o.y = a.y + c.y; o.z = a.z + c.z; o.w = a.w + c.w;
        reinterpret_cast<float4*>(out)[i] = o;
    }
}

// ---------------- launch ----------------
extern "C" void kernel_launch(void* const* d_in, const int* in_sizes, int n_in,
                              void* d_out, int out_size)
{
    const float* x    = (const float*)d_in[0];
    const float* ef   = (const float*)d_in[1];
    const float* flow = (const float*)d_in[2];
    const float* w1   = (const float*)d_in[3];
    const float* b1   = (const float*)d_in[4];
    const float* w2   = (const float*)d_in[5];
    const float* b2   = (const float*)d_in[6];
    const float* w3   = (const float*)d_in[7];
    const float* b3   = (const float*)d_in[8];
    const float* wgt  = (const float*)d_in[9];
    float* out = (float*)d_out;

    const int B = in_sizes[0] / (64 * HWc);  // = 2

    float *h1, *h2, *ppo, *pdp;
    cudaGetSymbolAddress((void**)&h1,  g_h1);
    cudaGetSymbolAddress((void**)&h2,  g_h2);
    cudaGetSymbolAddress((void**)&ppo, g_po);
    cudaGetSymbolAddress((void**)&pdp, g_dp);

    // conv1: 128 -> 64, leaky. Grid (4,8,B*2)
    conv3x3_kernel<128, 32, 2, true, false><<<dim3(4, 8, B * 2), 256>>>(ef, w1, b1, h1, nullptr);
    // conv2: 64 -> 64, leaky
    conv3x3_kernel<64, 32, 2, true, false><<<dim3(4, 8, B * 2), 256>>>(h1, w2, b2, h2, nullptr);
    // conv3: 64 -> 432, fused tanh/flow/sigmoid epilogue
    conv3x3_kernel<64, 24, 18, false, true><<<dim3(4, 8, B * 18), 256>>>(h2, w3, b3, ppo, flow);
    // deformable gather + einsum, 2-way group split
    deform_kernel<<<dim3(8, 16, B * NSPLIT), 128>>>(x, ppo, wgt, pdp);
    // combine partial sums -> out
    int n4 = B * 64 * HWc / 4;
    combine_kernel<<<(n4 + 255) / 256, 256>>>(pdp, out, n4);
}